// round 1
// baseline (speedup 1.0000x reference)
#include <cuda_runtime.h>
#include <cuda_bf16.h>

// ScalableHashGrid: InstantNGP-style multires hash grid encoding.
// 2^20 points x 10 levels x 4 feature dims, trilinear interp of 8 corners.
// Levels 0-2 dense (res 16/32/64), levels 3-9 hashed into 2^21-entry tables.

namespace {
constexpr int N_POINTS   = 1 << 20;
constexpr int NUM_LEVELS = 10;
constexpr unsigned HASH_MASK = (1u << 21) - 1u;
constexpr unsigned PRIME_Y = 2654435761u;
constexpr unsigned PRIME_Z = 805459861u;
}

// Per-level resolution and element offset into the concatenated table.
// Offsets derived from SIZES = ceil8(min((r+1)^3, 2^21)):
//   4920, 35944, 274632, then 7 x 2097152.
__constant__ int c_res[NUM_LEVELS] = {16, 32, 64, 128, 256, 512, 1024, 2048, 4096, 8192};
__constant__ int c_off[NUM_LEVELS] = {0, 4920, 40864, 315496, 2412648,
                                      4509800, 6606952, 8704104, 10801256, 12898408};

__global__ __launch_bounds__(256)
void hashgrid_kernel(const float* __restrict__ x,
                     const float4* __restrict__ table,
                     float4* __restrict__ out)
{
    const int t = blockIdx.x * blockDim.x + threadIdx.x;   // grid sized exactly
    const int l = t >> 20;              // level (warp-uniform)
    const int n = t & (N_POINTS - 1);   // point

    // Load point, map to [0,1], then to grid position.
    const float px_in = x[3 * n + 0];
    const float py_in = x[3 * n + 1];
    const float pz_in = x[3 * n + 2];

    const int   res   = c_res[l];
    const float scale = (float)res - 1.0f;

    const float posx = ((px_in + 1.0f) * 0.5f) * scale + 0.5f;
    const float posy = ((py_in + 1.0f) * 0.5f) * scale + 0.5f;
    const float posz = ((pz_in + 1.0f) * 0.5f) * scale + 0.5f;

    const float flx = floorf(posx);
    const float fly = floorf(posy);
    const float flz = floorf(posz);
    const float fx = posx - flx;
    const float fy = posy - fly;
    const float fz = posz - flz;
    const unsigned ix = (unsigned)flx;
    const unsigned iy = (unsigned)fly;
    const unsigned iz = (unsigned)flz;

    // Corner c: offsets (c&1, (c>>1)&1, (c>>2)&1), matching CORNER_OFFS.
    unsigned idx[8];
    if (l < 3) {
        // Dense level: idx = x + y*(res+1) + z*(res+1)^2
        const unsigned r1 = (unsigned)(res + 1);
        const unsigned y0 = iy * r1,        y1 = (iy + 1u) * r1;
        const unsigned z0 = iz * r1 * r1,   z1 = (iz + 1u) * r1 * r1;
        idx[0] = ix      + y0 + z0;
        idx[1] = ix + 1u + y0 + z0;
        idx[2] = ix      + y1 + z0;
        idx[3] = ix + 1u + y1 + z0;
        idx[4] = ix      + y0 + z1;
        idx[5] = ix + 1u + y0 + z1;
        idx[6] = ix      + y1 + z1;
        idx[7] = ix + 1u + y1 + z1;
    } else {
        // Hashed level: (x*1 ^ y*P1 ^ z*P2) & (2^21-1)
        const unsigned hx0 = ix,                 hx1 = ix + 1u;
        const unsigned hy0 = iy * PRIME_Y,       hy1 = (iy + 1u) * PRIME_Y;
        const unsigned hz0 = iz * PRIME_Z,       hz1 = (iz + 1u) * PRIME_Z;
        idx[0] = (hx0 ^ hy0 ^ hz0) & HASH_MASK;
        idx[1] = (hx1 ^ hy0 ^ hz0) & HASH_MASK;
        idx[2] = (hx0 ^ hy1 ^ hz0) & HASH_MASK;
        idx[3] = (hx1 ^ hy1 ^ hz0) & HASH_MASK;
        idx[4] = (hx0 ^ hy0 ^ hz1) & HASH_MASK;
        idx[5] = (hx1 ^ hy0 ^ hz1) & HASH_MASK;
        idx[6] = (hx0 ^ hy1 ^ hz1) & HASH_MASK;
        idx[7] = (hx1 ^ hy1 ^ hz1) & HASH_MASK;
    }

    // Issue all 8 gathers up front for maximum MLP.
    const float4* __restrict__ tab = table + c_off[l];
    float4 e[8];
#pragma unroll
    for (int c = 0; c < 8; c++) {
        e[c] = __ldg(&tab[idx[c]]);
    }

    const float wx[2] = {1.0f - fx, fx};
    const float wy[2] = {1.0f - fy, fy};
    const float wz[2] = {1.0f - fz, fz};

    float4 acc = make_float4(0.f, 0.f, 0.f, 0.f);
#pragma unroll
    for (int c = 0; c < 8; c++) {
        const float w = wx[c & 1] * wy[(c >> 1) & 1] * wz[(c >> 2) & 1];
        acc.x += w * e[c].x;
        acc.y += w * e[c].y;
        acc.z += w * e[c].z;
        acc.w += w * e[c].w;
    }

    // out[n][l*4 .. l*4+4) -> float4 at element n*10 + l (16B aligned).
    out[n * NUM_LEVELS + l] = acc;
}

extern "C" void kernel_launch(void* const* d_in, const int* in_sizes, int n_in,
                              void* d_out, int out_size)
{
    const float*  x     = (const float*)d_in[0];
    const float4* table = (const float4*)d_in[1];
    float4*       out   = (float4*)d_out;

    const int total   = N_POINTS * NUM_LEVELS;   // 10485760
    const int threads = 256;
    const int blocks  = total / threads;         // 40960, exact
    hashgrid_kernel<<<blocks, threads>>>(x, table, out);
}